// round 1
// baseline (speedup 1.0000x reference)
#include <cuda_runtime.h>
#include <cstddef>

// Problem constants
#define B_  4
#define T_  2048
#define C_  1024
#define H_  16
#define D_  64
#define M_ROWS (B_ * T_)          // 8192

// Scratch buffers (allocation-free rule: __device__ globals)
__device__ float g_qkv[(size_t)M_ROWS * (3 * C_)];   // [8192, 3072]
__device__ float g_att[(size_t)M_ROWS * C_];         // [8192, 1024]

// ---------------------------------------------------------------------------
// GEMM + bias:  C[M,N] = A[M,K] @ W[K,N] + bias[N]
// 64x64 block tile, BK=16, 256 threads, 4x4 register micro-tile.
// As stored transposed [BK][68] (padded, 272B rows -> 16B-aligned float4),
// Bs [BK][64]. Inner loop: 2x LDS.128 + 16 FFMA per k.
// ---------------------------------------------------------------------------
#define GBM 64
#define GBN 64
#define GBK 16

__global__ __launch_bounds__(256) void gemm_bias_kernel(
    const float* __restrict__ A, const float* __restrict__ W,
    const float* __restrict__ bias, float* __restrict__ Cmat,
    int M, int N, int K)
{
    __shared__ float As[GBK][68];   // transposed A tile (padded)
    __shared__ float Bs[GBK][GBN];

    const int tid = threadIdx.x;
    const int ty  = tid >> 4;       // 0..15
    const int tx  = tid & 15;       // 0..15
    const int bm  = blockIdx.y * GBM;
    const int bn  = blockIdx.x * GBN;

    // global load indices
    const int a_row  = tid >> 2;           // 0..63
    const int a_col4 = (tid & 3) * 4;      // 0,4,8,12
    const int b_row  = tid >> 4;           // 0..15
    const int b_col4 = (tid & 15) * 4;     // 0..60

    const float* a_src = A + (size_t)(bm + a_row) * K + a_col4;
    const float* b_src = W + (size_t)b_row * N + bn + b_col4;

    float acc[4][4] = {};

    for (int k0 = 0; k0 < K; k0 += GBK) {
        float4 av = *(const float4*)(a_src + k0);
        As[a_col4 + 0][a_row] = av.x;
        As[a_col4 + 1][a_row] = av.y;
        As[a_col4 + 2][a_row] = av.z;
        As[a_col4 + 3][a_row] = av.w;
        float4 bv = *(const float4*)(b_src + (size_t)k0 * N);
        *(float4*)&Bs[b_row][b_col4] = bv;
        __syncthreads();

        #pragma unroll
        for (int k = 0; k < GBK; k++) {
            float4 a4 = *(const float4*)&As[k][ty * 4];
            float4 b4 = *(const float4*)&Bs[k][tx * 4];
            float ar[4] = {a4.x, a4.y, a4.z, a4.w};
            float br[4] = {b4.x, b4.y, b4.z, b4.w};
            #pragma unroll
            for (int i = 0; i < 4; i++)
                #pragma unroll
                for (int j = 0; j < 4; j++)
                    acc[i][j] += ar[i] * br[j];
        }
        __syncthreads();
    }

    // epilogue: bias + store (float4)
    float4 bb = *(const float4*)&bias[bn + tx * 4];
    #pragma unroll
    for (int i = 0; i < 4; i++) {
        float4 o;
        o.x = acc[i][0] + bb.x;
        o.y = acc[i][1] + bb.y;
        o.z = acc[i][2] + bb.z;
        o.w = acc[i][3] + bb.w;
        *(float4*)&Cmat[(size_t)(bm + ty * 4 + i) * N + bn + tx * 4] = o;
    }
}

// ---------------------------------------------------------------------------
// Flash attention (fp32, online softmax, causal tile skipping).
// Grid: (32 q-tiles, 64 batch*head). Block: 256 threads.
// Q and K stored d-major (transposed) in smem so S-compute is the same
// conflict-free float4 pattern as the GEMM. V stored key-major for PV.
// smem stride 68 floats = 272 B (16B multiple -> aligned float4).
// ---------------------------------------------------------------------------
#define AT_STRIDE 68
#define AT_TILE   (64 * AT_STRIDE)

__global__ __launch_bounds__(256) void attn_kernel(
    const float* __restrict__ qkv, float* __restrict__ y)
{
    const int qt = blockIdx.x;         // query tile 0..31
    const int bh = blockIdx.y;         // 0..63
    const int b  = bh >> 4;
    const int h  = bh & 15;

    extern __shared__ float sm[];
    float* Qt = sm;                 // [d][r]  64x68
    float* Kt = sm + AT_TILE;       // [d][kr]
    float* Vs = sm + 2 * AT_TILE;   // [kr][d]
    float* Ss = sm + 3 * AT_TILE;   // [r][kc]
    __shared__ float m_s[64], l_s[64], al_s[64];

    const int tid = threadIdx.x;
    const int ty  = tid >> 4;       // 0..15
    const int tx  = tid & 15;       // 0..15
    const float scale = 0.125f;     // 1/sqrt(64)

    // Load Q tile transposed + pre-scaled
    {
        const int r = tid >> 2;
        const int dbase = (tid & 3) * 16;
        const float* src = qkv + (size_t)(b * T_ + qt * 64 + r) * (3 * C_) + h * D_ + dbase;
        #pragma unroll
        for (int u = 0; u < 4; u++) {
            float4 v = *(const float4*)(src + u * 4);
            int d0 = dbase + u * 4;
            Qt[(d0 + 0) * AT_STRIDE + r] = v.x * scale;
            Qt[(d0 + 1) * AT_STRIDE + r] = v.y * scale;
            Qt[(d0 + 2) * AT_STRIDE + r] = v.z * scale;
            Qt[(d0 + 3) * AT_STRIDE + r] = v.w * scale;
        }
    }
    if (tid < 64) { m_s[tid] = -1e30f; l_s[tid] = 0.0f; }

    float acc[4][4] = {};
    __syncthreads();

    const int nkt = qt + 1;   // causal: only tiles with keys <= queries
    for (int kt = 0; kt < nkt; kt++) {
        // Load K (transposed) and V tiles
        {
            const int kr = tid >> 2;
            const int dbase = (tid & 3) * 16;
            const size_t rowoff = (size_t)(b * T_ + kt * 64 + kr) * (3 * C_);
            const float* ksrc = qkv + rowoff + C_     + h * D_ + dbase;
            const float* vsrc = qkv + rowoff + 2 * C_ + h * D_ + dbase;
            #pragma unroll
            for (int u = 0; u < 4; u++) {
                int d0 = dbase + u * 4;
                float4 kv = *(const float4*)(ksrc + u * 4);
                Kt[(d0 + 0) * AT_STRIDE + kr] = kv.x;
                Kt[(d0 + 1) * AT_STRIDE + kr] = kv.y;
                Kt[(d0 + 2) * AT_STRIDE + kr] = kv.z;
                Kt[(d0 + 3) * AT_STRIDE + kr] = kv.w;
                float4 vv = *(const float4*)(vsrc + u * 4);
                *(float4*)&Vs[kr * AT_STRIDE + d0] = vv;
            }
        }
        __syncthreads();

        // S = (Q*scale) @ K^T   (4x4 micro-tile per thread)
        float s[4][4] = {};
        #pragma unroll 8
        for (int k = 0; k < 64; k++) {
            float4 a4 = *(const float4*)&Qt[k * AT_STRIDE + ty * 4];
            float4 b4 = *(const float4*)&Kt[k * AT_STRIDE + tx * 4];
            float ar[4] = {a4.x, a4.y, a4.z, a4.w};
            float br[4] = {b4.x, b4.y, b4.z, b4.w};
            #pragma unroll
            for (int i = 0; i < 4; i++)
                #pragma unroll
                for (int j = 0; j < 4; j++)
                    s[i][j] += ar[i] * br[j];
        }

        // Write S with causal mask (only the diagonal tile needs masking)
        const bool diag = (kt == qt);
        #pragma unroll
        for (int i = 0; i < 4; i++) {
            int r = ty * 4 + i;
            #pragma unroll
            for (int j = 0; j < 4; j++) {
                int c = tx * 4 + j;
                float v = s[i][j];
                if (diag && c > r) v = -1e30f;
                Ss[r * AT_STRIDE + c] = v;
            }
        }
        __syncthreads();

        // Online softmax: warp w handles rows [w*8, w*8+8)
        {
            const int warp = tid >> 5, lane = tid & 31;
            #pragma unroll
            for (int rr = 0; rr < 8; rr++) {
                int r = warp * 8 + rr;
                float s0 = Ss[r * AT_STRIDE + lane];
                float s1 = Ss[r * AT_STRIDE + lane + 32];
                float mx = fmaxf(s0, s1);
                #pragma unroll
                for (int off = 16; off; off >>= 1)
                    mx = fmaxf(mx, __shfl_xor_sync(0xffffffffu, mx, off));
                float m_old = m_s[r];
                float m_new = fmaxf(m_old, mx);
                float p0 = __expf(s0 - m_new);
                float p1 = __expf(s1 - m_new);
                Ss[r * AT_STRIDE + lane] = p0;
                Ss[r * AT_STRIDE + lane + 32] = p1;
                float sum = p0 + p1;
                #pragma unroll
                for (int off = 16; off; off >>= 1)
                    sum += __shfl_xor_sync(0xffffffffu, sum, off);
                if (lane == 0) {
                    float al = __expf(m_old - m_new);
                    al_s[r] = al;
                    l_s[r]  = l_s[r] * al + sum;
                    m_s[r]  = m_new;
                }
            }
        }
        __syncthreads();

        // O = O*alpha + P @ V
        #pragma unroll
        for (int i = 0; i < 4; i++) {
            float al = al_s[ty * 4 + i];
            #pragma unroll
            for (int j = 0; j < 4; j++) acc[i][j] *= al;
        }
        #pragma unroll 8
        for (int k = 0; k < 64; k++) {
            float4 b4 = *(const float4*)&Vs[k * AT_STRIDE + tx * 4];
            float br[4] = {b4.x, b4.y, b4.z, b4.w};
            #pragma unroll
            for (int i = 0; i < 4; i++) {
                float p = Ss[(ty * 4 + i) * AT_STRIDE + k];
                #pragma unroll
                for (int j = 0; j < 4; j++)
                    acc[i][j] += p * br[j];
            }
        }
        __syncthreads();
    }

    // Normalize and write y[b, t, h*64 + d]
    #pragma unroll
    for (int i = 0; i < 4; i++) {
        int r = ty * 4 + i;
        float inv = 1.0f / l_s[r];
        float4 o;
        o.x = acc[i][0] * inv;
        o.y = acc[i][1] * inv;
        o.z = acc[i][2] * inv;
        o.w = acc[i][3] * inv;
        *(float4*)&y[(size_t)(b * T_ + qt * 64 + r) * C_ + h * D_ + tx * 4] = o;
    }
}

// ---------------------------------------------------------------------------
// Launch
// ---------------------------------------------------------------------------
extern "C" void kernel_launch(void* const* d_in, const int* in_sizes, int n_in,
                              void* d_out, int out_size)
{
    const float* x      = (const float*)d_in[0];
    const float* w_attn = (const float*)d_in[1];
    const float* b_attn = (const float*)d_in[2];
    const float* w_proj = (const float*)d_in[3];
    const float* b_proj = (const float*)d_in[4];
    float* out = (float*)d_out;

    float *qkv, *att;
    cudaGetSymbolAddress((void**)&qkv, g_qkv);
    cudaGetSymbolAddress((void**)&att, g_att);

    const int attn_smem = 4 * AT_TILE * (int)sizeof(float);   // 69632 B
    cudaFuncSetAttribute(attn_kernel,
                         cudaFuncAttributeMaxDynamicSharedMemorySize, attn_smem);

    dim3 blk(256);

    // 1) qkv = x @ W_attn + b_attn      [8192,3072]
    gemm_bias_kernel<<<dim3((3 * C_) / GBN, M_ROWS / GBM), blk>>>(
        x, w_attn, b_attn, qkv, M_ROWS, 3 * C_, C_);

    // 2) flash attention -> att [8192,1024]
    attn_kernel<<<dim3(T_ / 64, B_ * H_), blk, attn_smem>>>(qkv, att);

    // 3) out = att @ W_proj + b_proj    [8192,1024]
    gemm_bias_kernel<<<dim3(C_ / GBN, M_ROWS / GBM), blk>>>(
        att, w_proj, b_proj, out, M_ROWS, C_, C_);
}

// round 2
// speedup vs baseline: 1.5282x; 1.5282x over previous
#include <cuda_runtime.h>
#include <cstdint>
#include <cstddef>

// Problem constants
#define B_  4
#define T_  2048
#define C_  1024
#define H_  16
#define D_  64
#define M_ROWS (B_ * T_)          // 8192

// Scratch (allocation-free rule: __device__ globals)
__device__ float g_qkv[(size_t)M_ROWS * (3 * C_)];   // [8192, 3072]
__device__ float g_att[(size_t)M_ROWS * C_];         // [8192, 1024]

// ---------------------------------------------------------------------------
// tf32 helpers
// ---------------------------------------------------------------------------
__device__ __forceinline__ float to_tf32(float x) {
    float y;
    asm("cvt.rna.tf32.f32 %0, %1;" : "=f"(y) : "f"(x));
    return y;
}

__device__ __forceinline__ void mma_tf32(float* d, const uint32_t* a, const uint32_t* b) {
    asm volatile(
        "mma.sync.aligned.m16n8k8.row.col.f32.tf32.tf32.f32 "
        "{%0,%1,%2,%3}, {%4,%5,%6,%7}, {%8,%9}, {%0,%1,%2,%3};\n"
        : "+f"(d[0]), "+f"(d[1]), "+f"(d[2]), "+f"(d[3])
        : "r"(a[0]), "r"(a[1]), "r"(a[2]), "r"(a[3]), "r"(b[0]), "r"(b[1]));
}

__device__ __forceinline__ uint32_t ldsf(const float* p) {
    return __float_as_uint(*p);
}

// ---------------------------------------------------------------------------
// GEMM + bias via tf32 tensor cores.
// C[M,N] = A[M,K] @ W[K,N] + bias[N]
// Block tile 128x128, BK=16, 256 threads (8 warps, 2x4 warp grid, 64x32/warp).
// As row-major [128][20]  (stride 20 == 4 mod 32 -> conflict-free A frags)
// Bs row-major [16][136]  (stride 136 == 8 mod 32 -> conflict-free B frags)
// ---------------------------------------------------------------------------
#define GBM 128
#define GBN 128
#define GBK 16
#define AST 20
#define BST 136

__global__ __launch_bounds__(256) void gemm_tc_kernel(
    const float* __restrict__ A, const float* __restrict__ W,
    const float* __restrict__ bias, float* __restrict__ Cmat,
    int M, int N, int K)
{
    __shared__ float As[GBM * AST];
    __shared__ float Bs[GBK * BST];

    const int tid  = threadIdx.x;
    const int warp = tid >> 5;
    const int lane = tid & 31;
    const int wm   = warp >> 2;          // 0..1 -> rows wm*64
    const int wn   = warp & 3;           // 0..3 -> cols wn*32
    const int gid  = lane >> 2;          // group id 0..7
    const int tig  = lane & 3;           // thread in group 0..3

    const int bm = blockIdx.y * GBM;
    const int bn = blockIdx.x * GBN;

    // G2S indices
    const int a_row  = tid >> 2;         // 0..63 (and +64)
    const int a_col4 = (tid & 3) * 4;
    const int b_row  = tid >> 4;         // 0..15
    const int b_col4 = (tid & 15) * 4;   // 0..60 (and +64)

    const float* a_src = A + (size_t)(bm + a_row) * K + a_col4;
    const float* b_src = W + (size_t)b_row * N + bn + b_col4;

    float acc[4][4][4] = {};             // [mi][ni][frag]

    for (int k0 = 0; k0 < K; k0 += GBK) {
        // A tile: rows a_row, a_row+64
        #pragma unroll
        for (int h = 0; h < 2; h++) {
            float4 v = *(const float4*)(a_src + (size_t)h * 64 * K + k0);
            float* dst = &As[(a_row + h * 64) * AST + a_col4];
            dst[0] = to_tf32(v.x); dst[1] = to_tf32(v.y);
            dst[2] = to_tf32(v.z); dst[3] = to_tf32(v.w);
        }
        // B tile: cols b_col4, b_col4+64
        #pragma unroll
        for (int h = 0; h < 2; h++) {
            float4 v = *(const float4*)(b_src + (size_t)k0 * N + h * 64);
            float* dst = &Bs[b_row * BST + b_col4 + h * 64];
            dst[0] = to_tf32(v.x); dst[1] = to_tf32(v.y);
            dst[2] = to_tf32(v.z); dst[3] = to_tf32(v.w);
        }
        __syncthreads();

        #pragma unroll
        for (int ks = 0; ks < GBK; ks += 8) {
            uint32_t af[4][4], bf[4][2];
            #pragma unroll
            for (int mi = 0; mi < 4; mi++) {
                const int r = wm * 64 + mi * 16 + gid;
                const int c = ks + tig;
                af[mi][0] = ldsf(&As[r * AST + c]);
                af[mi][1] = ldsf(&As[(r + 8) * AST + c]);
                af[mi][2] = ldsf(&As[r * AST + c + 4]);
                af[mi][3] = ldsf(&As[(r + 8) * AST + c + 4]);
            }
            #pragma unroll
            for (int ni = 0; ni < 4; ni++) {
                const int n = wn * 32 + ni * 8 + gid;
                const int k = ks + tig;
                bf[ni][0] = ldsf(&Bs[k * BST + n]);
                bf[ni][1] = ldsf(&Bs[(k + 4) * BST + n]);
            }
            #pragma unroll
            for (int mi = 0; mi < 4; mi++)
                #pragma unroll
                for (int ni = 0; ni < 4; ni++)
                    mma_tf32(acc[mi][ni], af[mi], bf[ni]);
        }
        __syncthreads();
    }

    // Epilogue: bias + store (float2 per fragment pair)
    #pragma unroll
    for (int mi = 0; mi < 4; mi++) {
        const int r0 = bm + wm * 64 + mi * 16 + gid;
        #pragma unroll
        for (int ni = 0; ni < 4; ni++) {
            const int c = bn + wn * 32 + ni * 8 + 2 * tig;
            float2 bb = *(const float2*)&bias[c];
            float2 o0, o1;
            o0.x = acc[mi][ni][0] + bb.x;
            o0.y = acc[mi][ni][1] + bb.y;
            o1.x = acc[mi][ni][2] + bb.x;
            o1.y = acc[mi][ni][3] + bb.y;
            *(float2*)&Cmat[(size_t)r0 * N + c]       = o0;
            *(float2*)&Cmat[(size_t)(r0 + 8) * N + c] = o1;
        }
    }
}

// ---------------------------------------------------------------------------
// Flash attention with tf32 tensor cores.
// Grid: (32 q-tiles, 64 batch*head). 256 threads, 8 warps (4x2 warp grid).
// Qs [64][68] row-major (q rows)      -> A frags (stride==4 mod 32, CF)
// Ks [64][68] row-major (k rows)      -> B frags col-major view (CF)
// Vs [64][72] row-major (k rows)      -> B frags (stride==8 mod 32, CF)
// Ss [64][68] scores / probs
// ---------------------------------------------------------------------------
#define QST 68
#define VST 72

__global__ __launch_bounds__(256) void attn_tc_kernel(
    const float* __restrict__ qkv, float* __restrict__ y)
{
    const int qt = blockIdx.x;
    const int bh = blockIdx.y;
    const int b  = bh >> 4;
    const int h  = bh & 15;

    extern __shared__ float sm[];
    float* Qs = sm;                    // 64*68
    float* Ks = Qs + 64 * QST;         // 64*68
    float* Vs = Ks + 64 * QST;         // 64*72
    float* Ss = Vs + 64 * VST;         // 64*68
    __shared__ float m_s[64], l_s[64], al_s[64];

    const int tid  = threadIdx.x;
    const int warp = tid >> 5;
    const int lane = tid & 31;
    const int wm   = warp >> 1;        // 0..3 -> rows wm*16
    const int wn   = warp & 1;         // 0..1 -> cols wn*32
    const int gid  = lane >> 2;
    const int tig  = lane & 3;
    const float scale = 0.125f;

    // Load Q tile (scaled, tf32-rounded)
    {
        const int r  = tid >> 2;                 // 0..63
        const int c0 = (tid & 3) * 16;
        const float* src = qkv + (size_t)(b * T_ + qt * 64 + r) * (3 * C_) + h * D_ + c0;
        #pragma unroll
        for (int u = 0; u < 4; u++) {
            float4 v = *(const float4*)(src + u * 4);
            float* dst = &Qs[r * QST + c0 + u * 4];
            dst[0] = to_tf32(v.x * scale); dst[1] = to_tf32(v.y * scale);
            dst[2] = to_tf32(v.z * scale); dst[3] = to_tf32(v.w * scale);
        }
    }
    if (tid < 64) { m_s[tid] = -1e30f; l_s[tid] = 0.0f; }

    float acc_o[4][4] = {};            // [ni][frag] persistent O accumulator
    __syncthreads();

    const int nkt = qt + 1;
    for (int kt = 0; kt < nkt; kt++) {
        // Load K,V tiles
        {
            const int r  = tid >> 2;
            const int c0 = (tid & 3) * 16;
            const size_t rowoff = (size_t)(b * T_ + kt * 64 + r) * (3 * C_);
            const float* ksrc = qkv + rowoff + C_     + h * D_ + c0;
            const float* vsrc = qkv + rowoff + 2 * C_ + h * D_ + c0;
            #pragma unroll
            for (int u = 0; u < 4; u++) {
                float4 kv = *(const float4*)(ksrc + u * 4);
                float* kd = &Ks[r * QST + c0 + u * 4];
                kd[0] = to_tf32(kv.x); kd[1] = to_tf32(kv.y);
                kd[2] = to_tf32(kv.z); kd[3] = to_tf32(kv.w);
                float4 vv = *(const float4*)(vsrc + u * 4);
                float* vd = &Vs[r * VST + c0 + u * 4];
                vd[0] = to_tf32(vv.x); vd[1] = to_tf32(vv.y);
                vd[2] = to_tf32(vv.z); vd[3] = to_tf32(vv.w);
            }
        }
        __syncthreads();

        // S = Q @ K^T  (each warp: 16 rows x 32 cols, 4 n-tiles, 8 k-steps)
        float acc_s[4][4] = {};
        #pragma unroll
        for (int ks = 0; ks < 64; ks += 8) {
            uint32_t af[4], bf[4][2];
            const int r = wm * 16 + gid;
            const int c = ks + tig;
            af[0] = ldsf(&Qs[r * QST + c]);
            af[1] = ldsf(&Qs[(r + 8) * QST + c]);
            af[2] = ldsf(&Qs[r * QST + c + 4]);
            af[3] = ldsf(&Qs[(r + 8) * QST + c + 4]);
            #pragma unroll
            for (int ni = 0; ni < 4; ni++) {
                const int n = wn * 32 + ni * 8 + gid;   // key row index
                bf[ni][0] = ldsf(&Ks[n * QST + ks + tig]);
                bf[ni][1] = ldsf(&Ks[n * QST + ks + tig + 4]);
            }
            #pragma unroll
            for (int ni = 0; ni < 4; ni++)
                mma_tf32(acc_s[ni], af, bf[ni]);
        }

        // Write S with causal mask
        {
            const bool diag = (kt == qt);
            const int r = wm * 16 + gid;
            #pragma unroll
            for (int ni = 0; ni < 4; ni++) {
                const int c = wn * 32 + ni * 8 + 2 * tig;
                float v0 = acc_s[ni][0], v1 = acc_s[ni][1];
                float v2 = acc_s[ni][2], v3 = acc_s[ni][3];
                if (diag) {
                    if (c > r)         v0 = -1e30f;
                    if (c + 1 > r)     v1 = -1e30f;
                    if (c > r + 8)     v2 = -1e30f;
                    if (c + 1 > r + 8) v3 = -1e30f;
                }
                Ss[r * QST + c]           = v0;
                Ss[r * QST + c + 1]       = v1;
                Ss[(r + 8) * QST + c]     = v2;
                Ss[(r + 8) * QST + c + 1] = v3;
            }
        }
        __syncthreads();

        // Online softmax: warp w -> rows [w*8, w*8+8)
        #pragma unroll
        for (int rr = 0; rr < 8; rr++) {
            const int r = warp * 8 + rr;
            float s0 = Ss[r * QST + lane];
            float s1 = Ss[r * QST + lane + 32];
            float mx = fmaxf(s0, s1);
            #pragma unroll
            for (int off = 16; off; off >>= 1)
                mx = fmaxf(mx, __shfl_xor_sync(0xffffffffu, mx, off));
            const float m_old = m_s[r];
            const float m_new = fmaxf(m_old, mx);
            const float p0 = __expf(s0 - m_new);
            const float p1 = __expf(s1 - m_new);
            Ss[r * QST + lane]      = to_tf32(p0);
            Ss[r * QST + lane + 32] = to_tf32(p1);
            float sum = p0 + p1;
            #pragma unroll
            for (int off = 16; off; off >>= 1)
                sum += __shfl_xor_sync(0xffffffffu, sum, off);
            if (lane == 0) {
                const float al = __expf(m_old - m_new);
                al_s[r] = al;
                l_s[r]  = l_s[r] * al + sum;
                m_s[r]  = m_new;
            }
        }
        __syncthreads();

        // O = O*alpha + P @ V
        {
            const int r = wm * 16 + gid;
            const float a0 = al_s[r];
            const float a8 = al_s[r + 8];
            #pragma unroll
            for (int ni = 0; ni < 4; ni++) {
                acc_o[ni][0] *= a0; acc_o[ni][1] *= a0;
                acc_o[ni][2] *= a8; acc_o[ni][3] *= a8;
            }
            #pragma unroll
            for (int ks = 0; ks < 64; ks += 8) {
                uint32_t af[4], bf[4][2];
                const int c = ks + tig;
                af[0] = ldsf(&Ss[r * QST + c]);
                af[1] = ldsf(&Ss[(r + 8) * QST + c]);
                af[2] = ldsf(&Ss[r * QST + c + 4]);
                af[3] = ldsf(&Ss[(r + 8) * QST + c + 4]);
                #pragma unroll
                for (int ni = 0; ni < 4; ni++) {
                    const int n = wn * 32 + ni * 8 + gid;   // d index
                    bf[ni][0] = ldsf(&Vs[(ks + tig) * VST + n]);
                    bf[ni][1] = ldsf(&Vs[(ks + tig + 4) * VST + n]);
                }
                #pragma unroll
                for (int ni = 0; ni < 4; ni++)
                    mma_tf32(acc_o[ni], af, bf[ni]);
            }
        }
        __syncthreads();
    }

    // Normalize and write y
    {
        const int r = wm * 16 + gid;
        const float inv0 = 1.0f / l_s[r];
        const float inv8 = 1.0f / l_s[r + 8];
        float* dst0 = &y[(size_t)(b * T_ + qt * 64 + r) * C_ + h * D_];
        float* dst8 = &y[(size_t)(b * T_ + qt * 64 + r + 8) * C_ + h * D_];
        #pragma unroll
        for (int ni = 0; ni < 4; ni++) {
            const int c = wn * 32 + ni * 8 + 2 * tig;
            float2 o0, o1;
            o0.x = acc_o[ni][0] * inv0; o0.y = acc_o[ni][1] * inv0;
            o1.x = acc_o[ni][2] * inv8; o1.y = acc_o[ni][3] * inv8;
            *(float2*)(dst0 + c) = o0;
            *(float2*)(dst8 + c) = o1;
        }
    }
}

// ---------------------------------------------------------------------------
// Launch
// ---------------------------------------------------------------------------
extern "C" void kernel_launch(void* const* d_in, const int* in_sizes, int n_in,
                              void* d_out, int out_size)
{
    const float* x      = (const float*)d_in[0];
    const float* w_attn = (const float*)d_in[1];
    const float* b_attn = (const float*)d_in[2];
    const float* w_proj = (const float*)d_in[3];
    const float* b_proj = (const float*)d_in[4];
    float* out = (float*)d_out;

    float *qkv, *att;
    cudaGetSymbolAddress((void**)&qkv, g_qkv);
    cudaGetSymbolAddress((void**)&att, g_att);

    const int attn_smem = (3 * 64 * QST + 64 * VST) * (int)sizeof(float);  // 70656 B
    cudaFuncSetAttribute(attn_tc_kernel,
                         cudaFuncAttributeMaxDynamicSharedMemorySize, attn_smem);

    dim3 blk(256);

    // 1) qkv = x @ W_attn + b_attn      [8192,3072]
    gemm_tc_kernel<<<dim3((3 * C_) / GBN, M_ROWS / GBM), blk>>>(
        x, w_attn, b_attn, qkv, M_ROWS, 3 * C_, C_);

    // 2) flash attention -> att [8192,1024]
    attn_tc_kernel<<<dim3(T_ / 64, B_ * H_), blk, attn_smem>>>(qkv, att);

    // 3) out = att @ W_proj + b_proj    [8192,1024]
    gemm_tc_kernel<<<dim3(C_ / GBN, M_ROWS / GBM), blk>>>(
        att, w_proj, b_proj, out, M_ROWS, C_, C_);
}

// round 5
// speedup vs baseline: 4.2704x; 2.7943x over previous
#include <cuda_runtime.h>
#include <cstdint>
#include <cstddef>

// Problem constants
#define B_  4
#define T_  2048
#define C_  1024
#define H_  16
#define D_  64
#define M_ROWS (B_ * T_)          // 8192

// Scratch (allocation-free rule: __device__ globals)
__device__ float g_qkv[(size_t)M_ROWS * (3 * C_)];   // [8192, 3072]
__device__ float g_att[(size_t)M_ROWS * C_];         // [8192, 1024]
__device__ float g_xr [(size_t)M_ROWS * C_];         // tf32-rounded x
__device__ float g_war[(size_t)C_ * (3 * C_)];       // tf32-rounded c_attn_w
__device__ float g_wpr[(size_t)C_ * C_];             // tf32-rounded c_proj_w

// ---------------------------------------------------------------------------
// helpers
// ---------------------------------------------------------------------------
__device__ __forceinline__ float to_tf32(float x) {
    float y;
    asm("cvt.rna.tf32.f32 %0, %1;" : "=f"(y) : "f"(x));
    return y;
}

__device__ __forceinline__ void mma_tf32(float* d, const uint32_t* a, const uint32_t* b) {
    asm volatile(
        "mma.sync.aligned.m16n8k8.row.col.f32.tf32.tf32.f32 "
        "{%0,%1,%2,%3}, {%4,%5,%6,%7}, {%8,%9}, {%0,%1,%2,%3};\n"
        : "+f"(d[0]), "+f"(d[1]), "+f"(d[2]), "+f"(d[3])
        : "r"(a[0]), "r"(a[1]), "r"(a[2]), "r"(a[3]), "r"(b[0]), "r"(b[1]));
}

__device__ __forceinline__ uint32_t ldsf(const float* p) {
    return __float_as_uint(*p);
}

__device__ __forceinline__ void cpa16(float* smem_dst, const float* gsrc) {
    uint32_t s = (uint32_t)__cvta_generic_to_shared(smem_dst);
    asm volatile("cp.async.cg.shared.global [%0], [%1], 16;" :: "r"(s), "l"(gsrc));
}
__device__ __forceinline__ void cpa_commit() {
    asm volatile("cp.async.commit_group;");
}
__device__ __forceinline__ void cpa_wait_all() {
    asm volatile("cp.async.wait_group 0;");
}

// ---------------------------------------------------------------------------
// tf32 pre-rounding pass (float4 vectorized)
// ---------------------------------------------------------------------------
__global__ void round_tf32_kernel(const float4* __restrict__ in,
                                  float4* __restrict__ out, int n4)
{
    int i = blockIdx.x * blockDim.x + threadIdx.x;
    if (i < n4) {
        float4 v = in[i];
        v.x = to_tf32(v.x); v.y = to_tf32(v.y);
        v.z = to_tf32(v.z); v.w = to_tf32(v.w);
        out[i] = v;
    }
}

// ---------------------------------------------------------------------------
// GEMM + bias, tf32 tensor cores, 2-stage cp.async pipeline.
// C[M,N] = A[M,K] @ W[K,N] + bias[N].  Inputs pre-rounded to tf32.
// Block 128x128, BK=32, 256 threads (8 warps 2x4, 64x32 each).
// As [stage][128][36] (36%32==4 -> CF A frags; 144B row, 16B aligned)
// Bs [stage][32][136] (136%32==8 -> CF B frags; 544B row)
// ---------------------------------------------------------------------------
#define GBM 128
#define GBN 128
#define GBK 32
#define AST 36
#define BST 136
#define A_TILE (GBM * AST)
#define B_TILE (GBK * BST)

template<bool ROUND_OUT>
__global__ __launch_bounds__(256) void gemm_tc_kernel(
    const float* __restrict__ A, const float* __restrict__ W,
    const float* __restrict__ bias, float* __restrict__ Cmat,
    int M, int N, int K)
{
    extern __shared__ float smem[];
    float* As = smem;                 // 2 stages
    float* Bs = smem + 2 * A_TILE;

    const int tid  = threadIdx.x;
    const int warp = tid >> 5;
    const int lane = tid & 31;
    const int wm   = warp >> 2;
    const int wn   = warp & 3;
    const int gid  = lane >> 2;
    const int tig  = lane & 3;

    const int bm = blockIdx.y * GBM;
    const int bn = blockIdx.x * GBN;

    // cp.async index plan: A tile 128x32 floats = 1024 f4 chunks, 4/thread
    //                      B tile 32x128 floats = 1024 f4 chunks, 4/thread
    const int a_r  = tid >> 1;            // base row for 2-chunk pairs? use flat
    (void)a_r;

    float acc[4][4][4] = {};

    auto load_tiles = [&](int st, int k0) {
        float* as = As + st * A_TILE;
        float* bs = Bs + st * B_TILE;
        #pragma unroll
        for (int ch = 0; ch < 4; ch++) {
            int idx = ch * 256 + tid;           // 0..1023
            int r  = idx >> 3;                  // 0..127
            int c4 = (idx & 7) * 4;             // 0..28
            cpa16(as + r * AST + c4, A + (size_t)(bm + r) * K + k0 + c4);
        }
        #pragma unroll
        for (int ch = 0; ch < 4; ch++) {
            int idx = ch * 256 + tid;
            int r  = idx >> 5;                  // 0..31
            int c4 = (idx & 31) * 4;            // 0..124
            cpa16(bs + r * BST + c4, W + (size_t)(k0 + r) * N + bn + c4);
        }
        cpa_commit();
    };

    load_tiles(0, 0);

    for (int k0 = 0; k0 < K; k0 += GBK) {
        cpa_wait_all();
        __syncthreads();
        const int st = (k0 / GBK) & 1;
        if (k0 + GBK < K) load_tiles(st ^ 1, k0 + GBK);

        const float* as = As + st * A_TILE;
        const float* bs = Bs + st * B_TILE;

        #pragma unroll
        for (int ks = 0; ks < GBK; ks += 8) {
            uint32_t af[4][4], bf[4][2];
            #pragma unroll
            for (int mi = 0; mi < 4; mi++) {
                const int r = wm * 64 + mi * 16 + gid;
                const int c = ks + tig;
                af[mi][0] = ldsf(&as[r * AST + c]);
                af[mi][1] = ldsf(&as[(r + 8) * AST + c]);
                af[mi][2] = ldsf(&as[r * AST + c + 4]);
                af[mi][3] = ldsf(&as[(r + 8) * AST + c + 4]);
            }
            #pragma unroll
            for (int ni = 0; ni < 4; ni++) {
                const int n = wn * 32 + ni * 8 + gid;
                const int k = ks + tig;
                bf[ni][0] = ldsf(&bs[k * BST + n]);
                bf[ni][1] = ldsf(&bs[(k + 4) * BST + n]);
            }
            #pragma unroll
            for (int mi = 0; mi < 4; mi++)
                #pragma unroll
                for (int ni = 0; ni < 4; ni++)
                    mma_tf32(acc[mi][ni], af[mi], bf[ni]);
        }
        __syncthreads();
    }

    #pragma unroll
    for (int mi = 0; mi < 4; mi++) {
        const int r0 = bm + wm * 64 + mi * 16 + gid;
        #pragma unroll
        for (int ni = 0; ni < 4; ni++) {
            const int c = bn + wn * 32 + ni * 8 + 2 * tig;
            float2 bb = *(const float2*)&bias[c];
            float2 o0, o1;
            o0.x = acc[mi][ni][0] + bb.x;
            o0.y = acc[mi][ni][1] + bb.y;
            o1.x = acc[mi][ni][2] + bb.x;
            o1.y = acc[mi][ni][3] + bb.y;
            if (ROUND_OUT) {
                o0.x = to_tf32(o0.x); o0.y = to_tf32(o0.y);
                o1.x = to_tf32(o1.x); o1.y = to_tf32(o1.y);
            }
            *(float2*)&Cmat[(size_t)r0 * N + c]       = o0;
            *(float2*)&Cmat[(size_t)(r0 + 8) * N + c] = o1;
        }
    }
}

// ---------------------------------------------------------------------------
// Flash attention, tf32 tensor cores, register softmax.
// Grid (32 q-tiles, 64 bh), 128 threads = 4 warps. Warp w owns q-rows
// [w*16, w*16+16) completely (16 x 64 S tile) -> softmax is warp-local.
// Q fragments persist in registers. P relayout (accum->A frag) via shfl.
// K/V tiles double-buffered with cp.async; ONE __syncthreads per KV tile.
// Ks [st][64][68], Vs [st][64][72]; qkv already tf32-rounded by producer.
// ---------------------------------------------------------------------------
#define KST 68
#define VST 72
#define K_TILE (64 * KST)
#define V_TILE (64 * VST)

__global__ __launch_bounds__(128) void attn_tc2_kernel(
    const float* __restrict__ qkv, float* __restrict__ y)
{
    const int qt = blockIdx.x;
    const int bh = blockIdx.y;
    const int b  = bh >> 4;
    const int h  = bh & 15;

    extern __shared__ float sm[];
    float* Ks = sm;                    // [2][64*KST]
    float* Vs = sm + 2 * K_TILE;       // [2][64*VST]

    const int tid  = threadIdx.x;
    const int warp = tid >> 5;
    const int lane = tid & 31;
    const int gid  = lane >> 2;
    const int tig  = lane & 3;

    const size_t qkv_row0 = (size_t)(b * T_) * (3 * C_);
    const int hc = h * D_;

    // ---- Stage Q into Ks[0], then pull fragments into registers ----
    {
        #pragma unroll
        for (int ch = 0; ch < 8; ch++) {
            int idx = ch * 128 + tid;          // 0..1023
            int r  = idx >> 4;
            int c4 = (idx & 15) * 4;
            float4 v = *(const float4*)(qkv + qkv_row0
                         + (size_t)(qt * 64 + r) * (3 * C_) + hc + c4);
            *(float4*)&Ks[r * KST + c4] = v;
        }
    }
    __syncthreads();

    uint32_t qf[8][4];
    {
        const int r = warp * 16 + gid;
        #pragma unroll
        for (int ks = 0; ks < 8; ks++) {
            const int c = ks * 8 + tig;
            // scale by 1/8 (exact power of two, no precision change)
            qf[ks][0] = __float_as_uint(Ks[r * KST + c] * 0.125f);
            qf[ks][1] = __float_as_uint(Ks[(r + 8) * KST + c] * 0.125f);
            qf[ks][2] = __float_as_uint(Ks[r * KST + c + 4] * 0.125f);
            qf[ks][3] = __float_as_uint(Ks[(r + 8) * KST + c + 4] * 0.125f);
        }
    }
    __syncthreads();

    // ---- cp.async loader for K/V tile kt into stage st ----
    auto load_kv = [&](int st, int kt) {
        float* kd = Ks + st * K_TILE;
        float* vd = Vs + st * V_TILE;
        const size_t base = qkv_row0 + (size_t)(kt * 64) * (3 * C_) + hc;
        #pragma unroll
        for (int ch = 0; ch < 8; ch++) {
            int idx = ch * 128 + tid;
            int r  = idx >> 4;
            int c4 = (idx & 15) * 4;
            const size_t roff = base + (size_t)r * (3 * C_);
            cpa16(kd + r * KST + c4, qkv + roff + C_ + c4);
            cpa16(vd + r * VST + c4, qkv + roff + 2 * C_ + c4);
        }
        cpa_commit();
    };

    load_kv(0, 0);

    float acc_o[8][4] = {};
    float m0 = -1e30f, m1 = -1e30f, l0 = 0.0f, l1 = 0.0f;
    const int r_loc0 = warp * 16 + gid;
    const int r_loc1 = r_loc0 + 8;

    for (int kt = 0; kt <= qt; kt++) {
        cpa_wait_all();
        __syncthreads();
        const int st = kt & 1;
        if (kt < qt) load_kv(st ^ 1, kt + 1);

        const float* ks_ = Ks + st * K_TILE;
        const float* vs_ = Vs + st * V_TILE;

        // ---- S = Q @ K^T : 16 x 64 per warp ----
        float s[8][4] = {};
        #pragma unroll
        for (int ks = 0; ks < 8; ks++) {
            uint32_t bf[8][2];
            const int kcol = ks * 8 + tig;       // d index
            #pragma unroll
            for (int ni = 0; ni < 8; ni++) {
                const int n = ni * 8 + gid;      // key row
                bf[ni][0] = ldsf(&ks_[n * KST + kcol]);
                bf[ni][1] = ldsf(&ks_[n * KST + kcol + 4]);
            }
            #pragma unroll
            for (int ni = 0; ni < 8; ni++)
                mma_tf32(s[ni], qf[ks], bf[ni]);
        }

        // ---- causal mask (diagonal tile only) ----
        if (kt == qt) {
            #pragma unroll
            for (int ni = 0; ni < 8; ni++) {
                const int c = ni * 8 + 2 * tig;
                if (c > r_loc0)     s[ni][0] = -1e30f;
                if (c + 1 > r_loc0) s[ni][1] = -1e30f;
                if (c > r_loc1)     s[ni][2] = -1e30f;
                if (c + 1 > r_loc1) s[ni][3] = -1e30f;
            }
        }

        // ---- register online softmax (rows warp-local) ----
        float mx0 = -1e30f, mx1 = -1e30f;
        #pragma unroll
        for (int ni = 0; ni < 8; ni++) {
            mx0 = fmaxf(mx0, fmaxf(s[ni][0], s[ni][1]));
            mx1 = fmaxf(mx1, fmaxf(s[ni][2], s[ni][3]));
        }
        mx0 = fmaxf(mx0, __shfl_xor_sync(0xffffffffu, mx0, 1));
        mx0 = fmaxf(mx0, __shfl_xor_sync(0xffffffffu, mx0, 2));
        mx1 = fmaxf(mx1, __shfl_xor_sync(0xffffffffu, mx1, 1));
        mx1 = fmaxf(mx1, __shfl_xor_sync(0xffffffffu, mx1, 2));

        const float mn0 = fmaxf(m0, mx0);
        const float mn1 = fmaxf(m1, mx1);
        const float al0 = __expf(m0 - mn0);
        const float al1 = __expf(m1 - mn1);
        m0 = mn0; m1 = mn1;

        float sum0 = 0.0f, sum1 = 0.0f;
        #pragma unroll
        for (int ni = 0; ni < 8; ni++) {
            float p0 = __expf(s[ni][0] - mn0);
            float p1 = __expf(s[ni][1] - mn0);
            float p2 = __expf(s[ni][2] - mn1);
            float p3 = __expf(s[ni][3] - mn1);
            sum0 += p0 + p1; sum1 += p2 + p3;
            s[ni][0] = to_tf32(p0); s[ni][1] = to_tf32(p1);
            s[ni][2] = to_tf32(p2); s[ni][3] = to_tf32(p3);
        }
        sum0 += __shfl_xor_sync(0xffffffffu, sum0, 1);
        sum0 += __shfl_xor_sync(0xffffffffu, sum0, 2);
        sum1 += __shfl_xor_sync(0xffffffffu, sum1, 1);
        sum1 += __shfl_xor_sync(0xffffffffu, sum1, 2);
        l0 = l0 * al0 + sum0;
        l1 = l1 * al1 + sum1;

        #pragma unroll
        for (int ni = 0; ni < 8; ni++) {
            acc_o[ni][0] *= al0; acc_o[ni][1] *= al0;
            acc_o[ni][2] *= al1; acc_o[ni][3] *= al1;
        }

        // ---- O += P @ V : P accum -> A-frag via shfl relayout ----
        const int base = lane & ~3;
        const int srcA = base + (tig >> 1);
        const bool odd = tig & 1;
        #pragma unroll
        for (int ks = 0; ks < 8; ks++) {
            float t0 = __shfl_sync(0xffffffffu, s[ks][0], srcA);
            float t1 = __shfl_sync(0xffffffffu, s[ks][1], srcA);
            float t2 = __shfl_sync(0xffffffffu, s[ks][2], srcA);
            float t3 = __shfl_sync(0xffffffffu, s[ks][3], srcA);
            float u0 = __shfl_sync(0xffffffffu, s[ks][0], srcA + 2);
            float u1 = __shfl_sync(0xffffffffu, s[ks][1], srcA + 2);
            float u2 = __shfl_sync(0xffffffffu, s[ks][2], srcA + 2);
            float u3 = __shfl_sync(0xffffffffu, s[ks][3], srcA + 2);
            uint32_t af[4];
            af[0] = __float_as_uint(odd ? t1 : t0);   // (gid,   tig)
            af[1] = __float_as_uint(odd ? t3 : t2);   // (gid+8, tig)
            af[2] = __float_as_uint(odd ? u1 : u0);   // (gid,   tig+4)
            af[3] = __float_as_uint(odd ? u3 : u2);   // (gid+8, tig+4)

            const int kr = ks * 8 + tig;              // key row (k dim)
            uint32_t bf[8][2];
            #pragma unroll
            for (int ni = 0; ni < 8; ni++) {
                const int n = ni * 8 + gid;           // d index
                bf[ni][0] = ldsf(&vs_[kr * VST + n]);
                bf[ni][1] = ldsf(&vs_[(kr + 4) * VST + n]);
            }
            #pragma unroll
            for (int ni = 0; ni < 8; ni++)
                mma_tf32(acc_o[ni], af, bf[ni]);
        }
    }

    // ---- epilogue: normalize, tf32-round (A operand of proj GEMM), store ----
    {
        const float inv0 = 1.0f / l0;
        const float inv1 = 1.0f / l1;
        float* dst0 = &y[(size_t)(b * T_ + qt * 64 + r_loc0) * C_ + hc];
        float* dst1 = &y[(size_t)(b * T_ + qt * 64 + r_loc1) * C_ + hc];
        #pragma unroll
        for (int ni = 0; ni < 8; ni++) {
            const int c = ni * 8 + 2 * tig;
            float2 o0, o1;
            o0.x = to_tf32(acc_o[ni][0] * inv0);
            o0.y = to_tf32(acc_o[ni][1] * inv0);
            o1.x = to_tf32(acc_o[ni][2] * inv1);
            o1.y = to_tf32(acc_o[ni][3] * inv1);
            *(float2*)(dst0 + c) = o0;
            *(float2*)(dst1 + c) = o1;
        }
    }
}

// ---------------------------------------------------------------------------
// Launch
// ---------------------------------------------------------------------------
extern "C" void kernel_launch(void* const* d_in, const int* in_sizes, int n_in,
                              void* d_out, int out_size)
{
    const float* x      = (const float*)d_in[0];
    const float* w_attn = (const float*)d_in[1];
    const float* b_attn = (const float*)d_in[2];
    const float* w_proj = (const float*)d_in[3];
    const float* b_proj = (const float*)d_in[4];
    float* out = (float*)d_out;

    float *qkv, *att, *xr, *war, *wpr;
    cudaGetSymbolAddress((void**)&qkv, g_qkv);
    cudaGetSymbolAddress((void**)&att, g_att);
    cudaGetSymbolAddress((void**)&xr,  g_xr);
    cudaGetSymbolAddress((void**)&war, g_war);
    cudaGetSymbolAddress((void**)&wpr, g_wpr);

    const int gemm_smem = (2 * A_TILE + 2 * B_TILE) * (int)sizeof(float);  // 71680
    const int attn_smem = (2 * K_TILE + 2 * V_TILE) * (int)sizeof(float);  // 71680
    cudaFuncSetAttribute(gemm_tc_kernel<true>,
                         cudaFuncAttributeMaxDynamicSharedMemorySize, gemm_smem);
    cudaFuncSetAttribute(gemm_tc_kernel<false>,
                         cudaFuncAttributeMaxDynamicSharedMemorySize, gemm_smem);
    cudaFuncSetAttribute(attn_tc2_kernel,
                         cudaFuncAttributeMaxDynamicSharedMemorySize, attn_smem);

    // 0) tf32 pre-rounding of GEMM inputs
    {
        int n4x = (M_ROWS * C_) / 4;
        int n4a = (C_ * 3 * C_) / 4;
        int n4p = (C_ * C_) / 4;
        round_tf32_kernel<<<(n4x + 255) / 256, 256>>>((const float4*)x, (float4*)xr, n4x);
        round_tf32_kernel<<<(n4a + 255) / 256, 256>>>((const float4*)w_attn, (float4*)war, n4a);
        round_tf32_kernel<<<(n4p + 255) / 256, 256>>>((const float4*)w_proj, (float4*)wpr, n4p);
    }

    // 1) qkv = x @ W_attn + b_attn (tf32-rounded output for attention)
    gemm_tc_kernel<true><<<dim3((3 * C_) / GBN, M_ROWS / GBM), 256, gemm_smem>>>(
        xr, war, b_attn, qkv, M_ROWS, 3 * C_, C_);

    // 2) flash attention -> att (tf32-rounded output for proj)
    attn_tc2_kernel<<<dim3(T_ / 64, B_ * H_), 128, attn_smem>>>(qkv, att);

    // 3) out = att @ W_proj + b_proj (full fp32 output)
    gemm_tc_kernel<false><<<dim3(C_ / GBN, M_ROWS / GBM), 256, gemm_smem>>>(
        att, wpr, b_proj, out, M_ROWS, C_, C_);
}